// round 3
// baseline (speedup 1.0000x reference)
#include <cuda_runtime.h>
#include <cuda_bf16.h>
#include <cstdint>

// Per-edge dot product: out[e] = sum_d h[src[e]][d] * h[dst[e]][d]
// E = 1e6, D = 256 (fixed), N = 1e5 nodes.
//
// Warp-per-edge. Each lane loads 2 float4 from the src row and 2 from the dst
// row (256 floats = 32 lanes * 8 floats), all 4 loads front-batched (MLP=4),
// then 5-step shfl butterfly reduce; lane 0 writes with streaming hint.
// The 102 MB node table is (just barely) L2-resident on GB300 (~126 MB L2);
// indices/output use streaming (evict-first) policy so they don't evict the
// reused table. LTS-throughput-bound: ~2 GB of L2 reads -> ~175 us floor at
// the ~6300 B/cyc LTS cap.

#ifndef D_FEAT
#define D_FEAT 256
#endif

// 1 if index arrays are int64, 0 if int32 (JAX may emit either depending on
// x64 mode). Written by the detection kernel, read by the main kernel; the
// kernel boundary inside the captured graph orders the write before the read.
__device__ int g_idx_is_64 = 1;

// If the data is really int64 with values in [0, n_nodes), every 8-byte word
// is a valid index. If it's int32, an 8-byte word decodes as v0 + v1*2^32,
// out of range unless v1 == 0 (prob ~1e-5 per probe); 64 probes all passing
// by accident has probability ~1e-320.
__global__ void detect_idx_kernel(const void* __restrict__ src_raw,
                                  long long n_nodes) {
    if (blockIdx.x == 0 && threadIdx.x == 0) {
        const long long* p = (const long long*)src_raw;
        int ok = 1;
        #pragma unroll 1
        for (int i = 0; i < 64; i++) {
            long long v = p[i];
            if (v < 0 || v >= n_nodes) { ok = 0; break; }
        }
        g_idx_is_64 = ok;
    }
}

__global__ __launch_bounds__(512, 4)
void edge_dot_kernel(const float* __restrict__ h,
                     const void* __restrict__ src_raw,
                     const void* __restrict__ dst_raw,
                     float* __restrict__ out,
                     int n_edges) {
    const int warp_id = (int)((blockIdx.x * (unsigned)blockDim.x + threadIdx.x) >> 5);
    const int lane = threadIdx.x & 31;
    if (warp_id >= n_edges) return;

    // Warp-uniform index load, streaming policy (no reuse -> don't pollute L2).
    long long s, d;
    if (g_idx_is_64) {
        s = __ldcs((const long long*)src_raw + warp_id);
        d = __ldcs((const long long*)dst_raw + warp_id);
    } else {
        s = (long long)__ldcs((const int*)src_raw + warp_id);
        d = (long long)__ldcs((const int*)dst_raw + warp_id);
    }

    // Rows are 256 floats = 64 float4, 1KB-aligned. Lane i takes float4 slots
    // i and i+32: consecutive lanes -> consecutive 16B -> fully coalesced.
    const float4* __restrict__ hs = (const float4*)(h + s * D_FEAT);
    const float4* __restrict__ hd = (const float4*)(h + d * D_FEAT);

    // Front-batch all 4 loads (MLP=4) before consuming any.
    float4 a0 = __ldg(hs + lane);
    float4 a1 = __ldg(hs + 32 + lane);
    float4 b0 = __ldg(hd + lane);
    float4 b1 = __ldg(hd + 32 + lane);

    float acc = a0.x * b0.x;
    acc = fmaf(a0.y, b0.y, acc);
    acc = fmaf(a0.z, b0.z, acc);
    acc = fmaf(a0.w, b0.w, acc);
    acc = fmaf(a1.x, b1.x, acc);
    acc = fmaf(a1.y, b1.y, acc);
    acc = fmaf(a1.z, b1.z, acc);
    acc = fmaf(a1.w, b1.w, acc);

    // Warp butterfly reduce (5 steps).
    #pragma unroll
    for (int off = 16; off > 0; off >>= 1)
        acc += __shfl_xor_sync(0xFFFFFFFFu, acc, off);

    // Streaming store: output has no reuse.
    if (lane == 0) __stcs(out + warp_id, acc);
}

extern "C" void kernel_launch(void* const* d_in, const int* in_sizes, int n_in,
                              void* d_out, int out_size) {
    const float* h   = (const float*)d_in[0];
    const void*  src = d_in[1];
    const void*  dst = d_in[2];
    float* out = (float*)d_out;

    // Output is [E, 1] float32 -> out_size == E, independent of index dtype.
    const int n_edges = out_size;
    const long long n_nodes = (long long)(in_sizes[0] / D_FEAT);

    detect_idx_kernel<<<1, 32>>>(src, n_nodes);

    // One warp per edge, 512 threads (16 warps) per block.
    const int warps_per_block = 512 / 32;
    const int blocks = (n_edges + warps_per_block - 1) / warps_per_block;
    edge_dot_kernel<<<blocks, 512>>>(h, src, dst, out, n_edges);
}

// round 9
// speedup vs baseline: 1.1735x; 1.1735x over previous
#include <cuda_runtime.h>
#include <cuda_bf16.h>
#include <cstdint>

// Per-edge dot product: out[e] = sum_d h[src[e]][d] * h[dst[e]][d]
// E = 1e6, D = 256, N = 1e5 nodes.
//
// R8 (= R7 resubmit; broker timeout, never executed): sm_103 ptxas requires
// .v8.b32 (256-bit) for L2::evict_last — so use LDG.256: one v8 load per
// lane covers the lane's full 32B share of a 1KB row. Warp handles TWO
// edges -> 4 front-batched LDG.256 (same bytes in flight as 8x LDG.128,
// half the instructions). evict_last pins the 102 MB node table in the
// ~126 MB L2 (R3 measured 512 MB DRAM spill, nothing saturated ->
// latency-bound). Indices/output keep streaming policy.

#ifndef D_FEAT
#define D_FEAT 256
#endif

// 1 if index arrays are int64, 0 if int32. Written by the detection kernel,
// read by the main kernel; kernel boundary in the graph orders write->read.
__device__ int g_idx_is_64 = 1;

// int64 data in [0, n_nodes) -> every 8-byte word valid. int32 data decodes
// as v0 + v1*2^32, out of range unless v1==0 (p~1e-5 per probe); 64 probes
// all passing by accident ~1e-320.
__global__ void detect_idx_kernel(const void* __restrict__ src_raw,
                                  long long n_nodes) {
    if (blockIdx.x == 0 && threadIdx.x == 0) {
        const long long* p = (const long long*)src_raw;
        int ok = 1;
        #pragma unroll 1
        for (int i = 0; i < 64; i++) {
            long long v = p[i];
            if (v < 0 || v >= n_nodes) { ok = 0; break; }
        }
        g_idx_is_64 = ok;
    }
}

struct F8 { float v[8]; };

// 256-bit table-row load: non-coherent + L2 evict_last (pin the node table).
// Requires 32-byte alignment (rows are 1KB aligned, lane offsets 32B).
__device__ __forceinline__ F8 ldg256_el(const float* p) {
    F8 r;
    asm("ld.global.nc.L2::evict_last.v8.b32 "
        "{%0,%1,%2,%3,%4,%5,%6,%7}, [%8];"
        : "=f"(r.v[0]), "=f"(r.v[1]), "=f"(r.v[2]), "=f"(r.v[3]),
          "=f"(r.v[4]), "=f"(r.v[5]), "=f"(r.v[6]), "=f"(r.v[7])
        : "l"(p));
    return r;
}

__global__ __launch_bounds__(256)
void edge_dot_kernel(const float* __restrict__ h,
                     const void* __restrict__ src_raw,
                     const void* __restrict__ dst_raw,
                     float* __restrict__ out,
                     int n_edges) {
    const int warp_id = (int)((blockIdx.x * (unsigned)blockDim.x + threadIdx.x) >> 5);
    const int lane = threadIdx.x & 31;
    const int e0 = warp_id * 2;
    if (e0 >= n_edges) return;
    const bool has1 = (e0 + 1 < n_edges);   // warp-uniform

    // Warp-uniform index loads, streaming policy.
    long long s0, d0, s1, d1;
    if (g_idx_is_64) {
        const long long* sp = (const long long*)src_raw;
        const long long* dp = (const long long*)dst_raw;
        s0 = __ldcs(sp + e0);
        d0 = __ldcs(dp + e0);
        s1 = has1 ? __ldcs(sp + e0 + 1) : s0;
        d1 = has1 ? __ldcs(dp + e0 + 1) : d0;
    } else {
        const int* sp = (const int*)src_raw;
        const int* dp = (const int*)dst_raw;
        s0 = (long long)__ldcs(sp + e0);
        d0 = (long long)__ldcs(dp + e0);
        s1 = has1 ? (long long)__ldcs(sp + e0 + 1) : s0;
        d1 = has1 ? (long long)__ldcs(dp + e0 + 1) : d0;
    }

    // Row = 256 floats = 1KB. Lane i owns floats [i*8, i*8+8): one 32B
    // LDG.256 per row per lane, consecutive lanes -> consecutive 32B.
    const int fo = lane * 8;
    const float* hs0 = h + s0 * D_FEAT + fo;
    const float* hd0 = h + d0 * D_FEAT + fo;
    const float* hs1 = h + s1 * D_FEAT + fo;
    const float* hd1 = h + d1 * D_FEAT + fo;

    // Front-batch all 4 LDG.256 (4KB/warp in flight) before consuming any.
    F8 a = ldg256_el(hs0);
    F8 b = ldg256_el(hd0);
    F8 c = ldg256_el(hs1);
    F8 f = ldg256_el(hd1);

    float acc0 = a.v[0] * b.v[0];
    #pragma unroll
    for (int i = 1; i < 8; i++) acc0 = fmaf(a.v[i], b.v[i], acc0);

    float acc1 = c.v[0] * f.v[0];
    #pragma unroll
    for (int i = 1; i < 8; i++) acc1 = fmaf(c.v[i], f.v[i], acc1);

    // Two interleaved butterfly reduces (independent shfl chains pipeline).
    #pragma unroll
    for (int off = 16; off > 0; off >>= 1) {
        acc0 += __shfl_xor_sync(0xFFFFFFFFu, acc0, off);
        acc1 += __shfl_xor_sync(0xFFFFFFFFu, acc1, off);
    }

    if (lane == 0) {
        __stcs(out + e0, acc0);
        if (has1) __stcs(out + e0 + 1, acc1);
    }
}

extern "C" void kernel_launch(void* const* d_in, const int* in_sizes, int n_in,
                              void* d_out, int out_size) {
    const float* h   = (const float*)d_in[0];
    const void*  src = d_in[1];
    const void*  dst = d_in[2];
    float* out = (float*)d_out;

    // Output is [E, 1] float32 -> out_size == E, independent of index dtype.
    const int n_edges = out_size;
    const long long n_nodes = (long long)(in_sizes[0] / D_FEAT);

    detect_idx_kernel<<<1, 32>>>(src, n_nodes);

    // Two edges per warp, 256 threads (8 warps) per block.
    const int n_warps = (n_edges + 1) / 2;
    const int warps_per_block = 256 / 32;
    const int blocks = (n_warps + warps_per_block - 1) / warps_per_block;
    edge_dot_kernel<<<blocks, 256>>>(h, src, dst, out, n_edges);
}

// round 11
// speedup vs baseline: 1.3613x; 1.1601x over previous
#include <cuda_runtime.h>
#include <cuda_bf16.h>
#include <cstdint>

// Per-edge dot product: out[e] = sum_d h[src[e]][d] * h[dst[e]][d]
// E = 1e6, D = 256, N = 1e5 nodes.
//
// R11 (= R10 resubmit; broker timeout, never executed): persistent
// grid-stride warps + index-prefetch software pipeline.
// R9 analysis: warp lifetime ~3300 cyc for ~1900 cyc of serial body
// (idx load ~600 -> row loads ~500 -> reduce ~200) + CTA churn from 62500
// one-shot blocks. Fix: (1) <=1216 persistent CTAs, each warp strides over
// many edge-pairs; (2) next pair's index loads issued while current row
// loads are in flight -> idx latency off the critical chain.
// Row loads stay LDG.256 (v8.b32 form required for the policy qualifier on
// sm_103); indices/output keep streaming policy.

#ifndef D_FEAT
#define D_FEAT 256
#endif

// 1 if index arrays are int64, 0 if int32. Written by the detection kernel,
// read by the main kernel; kernel boundary in the graph orders write->read.
__device__ int g_idx_is_64 = 1;

// int64 data in [0, n_nodes) -> every 8-byte word valid. int32 data decodes
// as v0 + v1*2^32, out of range unless v1==0 (p~1e-5 per probe); 64 probes
// all passing by accident ~1e-320.
__global__ void detect_idx_kernel(const void* __restrict__ src_raw,
                                  long long n_nodes) {
    if (blockIdx.x == 0 && threadIdx.x == 0) {
        const long long* p = (const long long*)src_raw;
        int ok = 1;
        #pragma unroll 1
        for (int i = 0; i < 64; i++) {
            long long v = p[i];
            if (v < 0 || v >= n_nodes) { ok = 0; break; }
        }
        g_idx_is_64 = ok;
    }
}

struct F8 { float v[8]; };

// 256-bit table-row load (rows 1KB-aligned, lane offsets 32B).
__device__ __forceinline__ F8 ldg256_el(const float* p) {
    F8 r;
    asm("ld.global.nc.L2::evict_last.v8.b32 "
        "{%0,%1,%2,%3,%4,%5,%6,%7}, [%8];"
        : "=f"(r.v[0]), "=f"(r.v[1]), "=f"(r.v[2]), "=f"(r.v[3]),
          "=f"(r.v[4]), "=f"(r.v[5]), "=f"(r.v[6]), "=f"(r.v[7])
        : "l"(p));
    return r;
}

// Load the 4 indices of edge-pair starting at e0 (streaming policy).
// Indices are < 1e5 -> store as int (saves registers in the pipeline).
__device__ __forceinline__ void load_pair_idx(
    const void* __restrict__ src_raw, const void* __restrict__ dst_raw,
    bool is64, int e0, int n_edges,
    int& s0, int& d0, int& s1, int& d1)
{
    const bool has1 = (e0 + 1 < n_edges);
    if (is64) {
        const long long* sp = (const long long*)src_raw;
        const long long* dp = (const long long*)dst_raw;
        s0 = (int)__ldcs(sp + e0);
        d0 = (int)__ldcs(dp + e0);
        s1 = has1 ? (int)__ldcs(sp + e0 + 1) : s0;
        d1 = has1 ? (int)__ldcs(dp + e0 + 1) : d0;
    } else {
        const int* sp = (const int*)src_raw;
        const int* dp = (const int*)dst_raw;
        s0 = __ldcs(sp + e0);
        d0 = __ldcs(dp + e0);
        s1 = has1 ? __ldcs(sp + e0 + 1) : s0;
        d1 = has1 ? __ldcs(dp + e0 + 1) : d0;
    }
}

__global__ __launch_bounds__(256)
void edge_dot_kernel(const float* __restrict__ h,
                     const void* __restrict__ src_raw,
                     const void* __restrict__ dst_raw,
                     float* __restrict__ out,
                     int n_edges) {
    const int lane = threadIdx.x & 31;
    const int warp = (int)((blockIdx.x * blockDim.x + threadIdx.x) >> 5);
    const int n_warps = (int)((gridDim.x * blockDim.x) >> 5);
    const int n_pairs = (n_edges + 1) >> 1;
    const bool is64 = (g_idx_is_64 != 0);

    int p = warp;
    if (p >= n_pairs) return;

    // Prologue: indices for the first pair.
    int s0, d0, s1, d1;
    load_pair_idx(src_raw, dst_raw, is64, 2 * p, n_edges, s0, d0, s1, d1);

    const int fo = lane * 8;

    #pragma unroll 1
    while (true) {
        const int e0 = 2 * p;
        const bool has1 = (e0 + 1 < n_edges);   // warp-uniform

        // Issue the 4 row loads for the current pair (front-batched).
        const float* hs0 = h + (long long)s0 * D_FEAT + fo;
        const float* hd0 = h + (long long)d0 * D_FEAT + fo;
        const float* hs1 = h + (long long)s1 * D_FEAT + fo;
        const float* hd1 = h + (long long)d1 * D_FEAT + fo;
        F8 a = ldg256_el(hs0);
        F8 b = ldg256_el(hd0);
        F8 c = ldg256_el(hs1);
        F8 f = ldg256_el(hd1);

        // Prefetch NEXT pair's indices while the row loads are in flight:
        // independent loads, so they issue before we stall on a..f.
        const int pn = p + n_warps;
        const bool have_next = (pn < n_pairs);
        int ns0 = 0, nd0 = 0, ns1 = 0, nd1 = 0;
        if (have_next)
            load_pair_idx(src_raw, dst_raw, is64, 2 * pn, n_edges,
                          ns0, nd0, ns1, nd1);

        // Consume the rows.
        float acc0 = a.v[0] * b.v[0];
        #pragma unroll
        for (int i = 1; i < 8; i++) acc0 = fmaf(a.v[i], b.v[i], acc0);

        float acc1 = c.v[0] * f.v[0];
        #pragma unroll
        for (int i = 1; i < 8; i++) acc1 = fmaf(c.v[i], f.v[i], acc1);

        // Two interleaved butterfly reduces.
        #pragma unroll
        for (int off = 16; off > 0; off >>= 1) {
            acc0 += __shfl_xor_sync(0xFFFFFFFFu, acc0, off);
            acc1 += __shfl_xor_sync(0xFFFFFFFFu, acc1, off);
        }

        if (lane == 0) {
            __stcs(out + e0, acc0);
            if (has1) __stcs(out + e0 + 1, acc1);
        }

        if (!have_next) break;
        p = pn;
        s0 = ns0; d0 = nd0; s1 = ns1; d1 = nd1;
    }
}

extern "C" void kernel_launch(void* const* d_in, const int* in_sizes, int n_in,
                              void* d_out, int out_size) {
    const float* h   = (const float*)d_in[0];
    const void*  src = d_in[1];
    const void*  dst = d_in[2];
    float* out = (float*)d_out;

    // Output is [E, 1] float32 -> out_size == E, independent of index dtype.
    const int n_edges = out_size;
    const long long n_nodes = (long long)(in_sizes[0] / D_FEAT);

    detect_idx_kernel<<<1, 32>>>(src, n_nodes);

    // Persistent-ish grid: ~8 blocks per SM (152 SMs on GB300), grid-stride
    // over edge-pairs. Cap by work so tiny inputs still work.
    const int n_pairs = (n_edges + 1) / 2;
    const int warps_per_block = 256 / 32;
    int blocks = (n_pairs + warps_per_block - 1) / warps_per_block;
    if (blocks > 1216) blocks = 1216;
    edge_dot_kernel<<<blocks, 256>>>(h, src, dst, out, n_edges);
}